// round 2
// baseline (speedup 1.0000x reference)
#include <cuda_runtime.h>
#include <cuda_fp16.h>
#include <cstdint>

// ======================= problem constants =======================
// B=128, T=1024, M=512 (GEMM N), P=256, K=512, rows = B*T = 131072
static constexpr int NB      = 128;
static constexpr int TLEN    = 1024;
static constexpr int MDIM    = 512;    // N of GEMM
static constexpr int KDIM    = 512;    // inner dim
static constexpr int MTILE   = 128;    // rows per CTA
static constexpr int NCHUNK  = 64;     // N per SMEM B chunk
static constexpr int NCHUNKS = MDIM / NCHUNK;   // 8

// padded row strides (in fp16 elements) -> +16B per row rotates bank groups,
// making all ldmatrix 8x8 tiles conflict-free
static constexpr int APAD = 520;       // 1040 B
static constexpr int BPAD = 520;

// SMEM: A[128][520] fp16 = 133120 B ; B[64][520] fp16 = 66560 B
static constexpr int SMEM_A_BYTES = MTILE * APAD * 2;
static constexpr int SMEM_B_BYTES = NCHUNK * BPAD * 2;
static constexpr int DYN_SMEM = SMEM_A_BYTES + SMEM_B_BYTES;   // 199680

// ======================= scratch (device globals; no allocs) =======================
__device__ float g_Qt[KDIM * NB];                    // Q transposed [c][b]
__device__ float g_wq[NB * MDIM];                    // wq[b][n]
__device__ __align__(16) __half g_U16[MDIM * KDIM];  // U_d as fp16, [n][k]

// ======================= helpers =======================
__device__ __forceinline__ uint32_t smem_u32(const void* p) {
    return (uint32_t)__cvta_generic_to_shared(p);
}

__device__ __forceinline__ uint32_t pack_h2(float a, float b) {
    __half2 h = __floats2half2_rn(a, b);
    return *reinterpret_cast<uint32_t*>(&h);
}

__device__ __forceinline__ void ldsm_x4(uint32_t addr, uint32_t& r0, uint32_t& r1,
                                        uint32_t& r2, uint32_t& r3) {
    asm volatile("ldmatrix.sync.aligned.m8n8.x4.shared.b16 {%0,%1,%2,%3}, [%4];"
                 : "=r"(r0), "=r"(r1), "=r"(r2), "=r"(r3) : "r"(addr));
}

__device__ __forceinline__ void mma16816(float& c0, float& c1, float& c2, float& c3,
                                         uint32_t a0, uint32_t a1, uint32_t a2, uint32_t a3,
                                         uint32_t b0, uint32_t b1) {
    asm volatile(
        "mma.sync.aligned.m16n8k16.row.col.f32.f16.f16.f32 "
        "{%0,%1,%2,%3}, {%4,%5,%6,%7}, {%8,%9}, {%0,%1,%2,%3};"
        : "+f"(c0), "+f"(c1), "+f"(c2), "+f"(c3)
        : "r"(a0), "r"(a1), "r"(a2), "r"(a3), "r"(b0), "r"(b1));
}

// ======================= kernel 1: pack Qt + U -> fp16 =======================
__global__ void __launch_bounds__(256, 1) pack_kernel(const float* __restrict__ dt,
                                                      const float* __restrict__ st,
                                                      const float* __restrict__ Ud) {
    int tid = blockIdx.x * blockDim.x + threadIdx.x;
    int stride = gridDim.x * blockDim.x;
    // Qt[c][b] = query[b][c]; query = concat(d_t, s_t) over c
    for (int i = tid; i < KDIM * NB; i += stride) {
        int c = i >> 7, b = i & (NB - 1);
        float v = (c < 256) ? dt[b * 256 + c] : st[b * 256 + (c - 256)];
        g_Qt[c * NB + b] = v;
    }
    // U_d[n][k] fp32 -> fp16 (plain layout; smem padding handled at copy time)
    for (int i = tid; i < MDIM * KDIM; i += stride)
        g_U16[i] = __float2half_rn(Ud[i]);
}

// ======================= kernel 2: wq[b][n] = sum_c q[b][c]*W_d[n][c] =======================
__global__ void __launch_bounds__(128, 1) wq_kernel(const float* __restrict__ Wd) {
    __shared__ float Ws[8 * KDIM];
    int nbase = blockIdx.x * 8;
    for (int i = threadIdx.x; i < 8 * KDIM; i += 128)
        Ws[i] = Wd[nbase * KDIM + i];
    __syncthreads();
    int b = threadIdx.x;
    float acc[8];
#pragma unroll
    for (int j = 0; j < 8; j++) acc[j] = 0.0f;
    for (int c = 0; c < KDIM; c++) {
        float qv = g_Qt[c * NB + b];
#pragma unroll
        for (int j = 0; j < 8; j++) acc[j] = fmaf(qv, Ws[j * KDIM + c], acc[j]);
    }
#pragma unroll
    for (int j = 0; j < 8; j++) g_wq[b * MDIM + nbase + j] = acc[j];
}

// ======================= kernel 3: fused GEMM(HMMA) + tanh + v-dot =======================
// grid = 1024 CTAs (131072/128 rows), 512 threads (16 warps).
// warp w: rowgrp = w>>1 (16 rows each), ngrp = w&1 (32 n each within a 64-n chunk)
__global__ void __launch_bounds__(512, 1) attn_gemm_kernel(const float* __restrict__ H,
                                                           const float* __restrict__ vd,
                                                           float* __restrict__ out) {
    extern __shared__ __align__(16) char dsm[];
    __half* smemA = reinterpret_cast<__half*>(dsm);
    __half* smemB = reinterpret_cast<__half*>(dsm + SMEM_A_BYTES);

    __shared__ float wq_s[MDIM];
    __shared__ float v_s[MDIM];
    __shared__ float score[MTILE];

    const int tid = threadIdx.x;
    const int wid = tid >> 5;
    const int lane = tid & 31;
    const int blk = blockIdx.x;
    const int batch = blk >> 3;               // 8 CTAs per batch row-block
    const size_t r0 = (size_t)blk * MTILE;

    // ---- per-CTA constants into smem ----
    for (int i = tid; i < MDIM; i += 512) {
        wq_s[i] = g_wq[batch * MDIM + i];
        v_s[i]  = vd[i];
    }
    if (tid < MTILE) score[tid] = 0.0f;

    // ---- load A: 128 rows x 512 K, fp32 -> fp16, padded rows ----
    // 8192 uint4 stores: idx -> row = idx>>6, c8 = idx&63 (8 halves each)
    {
#pragma unroll
        for (int it = 0; it < 16; it++) {
            int idx = tid + it * 512;
            int row = idx >> 6;
            int c8  = idx & 63;
            const float4* src = reinterpret_cast<const float4*>(
                H + (r0 + (size_t)row) * KDIM + c8 * 8);
            float4 f0 = src[0], f1 = src[1];
            uint4 u;
            u.x = pack_h2(f0.x, f0.y); u.y = pack_h2(f0.z, f0.w);
            u.z = pack_h2(f1.x, f1.y); u.w = pack_h2(f1.z, f1.w);
            *reinterpret_cast<uint4*>(smemA + row * APAD + c8 * 8) = u;
        }
    }

    // ---- ldmatrix base addresses (per lane) ----
    const int sub = lane >> 3;     // which 8x8 tile within x4
    const int l8  = lane & 7;
    const int rowgrp = wid >> 1;
    const int ngrp   = wid & 1;
    const int rbase  = rowgrp * 16;

    // A x4 tiles: t0 rows0-7/k0-7, t1 rows8-15/k0-7, t2 rows0-7/k8-15, t3 rows8-15/k8-15
    const uint32_t aAddrBase = smem_u32(smemA) +
        (uint32_t)(((rbase + (sub & 1) * 8 + l8) * APAD + (sub >> 1) * 8) * 2);
    // B x4 tiles: t0 n0-7/k0-7, t1 n0-7/k8-15, t2 n8-15/k0-7, t3 n8-15/k8-15
    const uint32_t bAddr0 = smem_u32(smemB) +
        (uint32_t)(((ngrp * 32 + (sub >> 1) * 8 + l8) * BPAD + (sub & 1) * 8) * 2);
    const uint32_t bAddr1 = bAddr0 + (uint32_t)(16 * BPAD * 2);

    const int qn = (lane & 3) * 2;   // n offset within an n8 tile held by this thread

    for (int c = 0; c < NCHUNKS; c++) {
        __syncthreads();   // prev chunk's compute done (and A store visible for c==0)

        // ---- load B chunk c: 64 n x 512 k fp16 from g_U16 (L2) ----
        {
            const uint4* src = reinterpret_cast<const uint4*>(g_U16 + c * NCHUNK * KDIM);
#pragma unroll
            for (int it = 0; it < 8; it++) {
                int idx = tid + it * 512;        // 4096 uint4
                int row = idx >> 6;              // n within chunk
                int c16 = idx & 63;              // 8-half group
                *reinterpret_cast<uint4*>(smemB + row * BPAD + c16 * 8) = src[idx];
            }
        }
        __syncthreads();

        // ---- K loop: 32 steps of k16 ----
        float acc[4][4];
#pragma unroll
        for (int t = 0; t < 4; t++)
#pragma unroll
            for (int j = 0; j < 4; j++) acc[t][j] = 0.0f;

#pragma unroll 4
        for (int ks = 0; ks < 32; ks++) {
            uint32_t a0, a1, a2, a3, p0, p1, p2, p3, q0, q1, q2, q3;
            ldsm_x4(aAddrBase + ks * 32, a0, a1, a2, a3);
            ldsm_x4(bAddr0 + ks * 32, p0, p1, p2, p3);
            ldsm_x4(bAddr1 + ks * 32, q0, q1, q2, q3);
            mma16816(acc[0][0], acc[0][1], acc[0][2], acc[0][3], a0, a1, a2, a3, p0, p1);
            mma16816(acc[1][0], acc[1][1], acc[1][2], acc[1][3], a0, a1, a2, a3, p2, p3);
            mma16816(acc[2][0], acc[2][1], acc[2][2], acc[2][3], a0, a1, a2, a3, q0, q1);
            mma16816(acc[3][0], acc[3][1], acc[3][2], acc[3][3], a0, a1, a2, a3, q2, q3);
        }

        // ---- fused epilogue for this n-chunk: tanh + v-dot ----
        const int nb = c * NCHUNK + ngrp * 32;
        float s0 = 0.0f, s1 = 0.0f;
#pragma unroll
        for (int t = 0; t < 4; t++) {
            int n = nb + t * 8 + qn;
            float w0 = wq_s[n], w1 = wq_s[n + 1];
            float v0 = v_s[n],  v1 = v_s[n + 1];
            s0 = fmaf(v0, tanhf(w0 + acc[t][0]), s0);
            s0 = fmaf(v1, tanhf(w1 + acc[t][1]), s0);
            s1 = fmaf(v0, tanhf(w0 + acc[t][2]), s1);
            s1 = fmaf(v1, tanhf(w1 + acc[t][3]), s1);
        }
        // quad reduce over lanes sharing a row (lane%4 varies n)
        s0 += __shfl_xor_sync(0xffffffffu, s0, 1);
        s0 += __shfl_xor_sync(0xffffffffu, s0, 2);
        s1 += __shfl_xor_sync(0xffffffffu, s1, 1);
        s1 += __shfl_xor_sync(0xffffffffu, s1, 2);
        if ((lane & 3) == 0) {
            atomicAdd(&score[rbase + (lane >> 2)], s0);
            atomicAdd(&score[rbase + 8 + (lane >> 2)], s1);
        }
    }
    __syncthreads();
    if (tid < MTILE) out[r0 + tid] = score[tid];
}

// ======================= kernel 4: softmax over T, in-place =======================
__global__ void __launch_bounds__(256, 1) softmax_kernel(float* __restrict__ out) {
    __shared__ float red[256];
    float* p = out + (size_t)blockIdx.x * TLEN;
    int tid = threadIdx.x;
    float v[4];
    float m = -1e30f;
#pragma unroll
    for (int j = 0; j < 4; j++) { v[j] = p[tid + j * 256]; m = fmaxf(m, v[j]); }
    red[tid] = m; __syncthreads();
    for (int s = 128; s > 0; s >>= 1) {
        if (tid < s) red[tid] = fmaxf(red[tid], red[tid + s]);
        __syncthreads();
    }
    float mx = red[0];
    __syncthreads();
    float sum = 0.0f;
#pragma unroll
    for (int j = 0; j < 4; j++) { v[j] = __expf(v[j] - mx); sum += v[j]; }
    red[tid] = sum; __syncthreads();
    for (int s = 128; s > 0; s >>= 1) {
        if (tid < s) red[tid] += red[tid + s];
        __syncthreads();
    }
    float inv = 1.0f / red[0];
#pragma unroll
    for (int j = 0; j < 4; j++) p[tid + j * 256] = v[j] * inv;
}

// ======================= launch =======================
extern "C" void kernel_launch(void* const* d_in, const int* in_sizes, int n_in,
                              void* d_out, int out_size) {
    const float *dt = nullptr, *st = nullptr, *H = nullptr;
    const float *W = nullptr, *U = nullptr, *v = nullptr;
    int c32768 = 0, c262144 = 0;
    for (int i = 0; i < n_in; i++) {
        int s = in_sizes[i];
        if (s == 32768)          { if (c32768++ == 0) dt = (const float*)d_in[i]; else st = (const float*)d_in[i]; }
        else if (s == 67108864)  { H = (const float*)d_in[i]; }
        else if (s == 262144)    { if (c262144++ == 0) W = (const float*)d_in[i]; else U = (const float*)d_in[i]; }
        else if (s == 512)       { v = (const float*)d_in[i]; }
        // scalar T intentionally ignored
    }
    float* out = (float*)d_out;

    cudaFuncSetAttribute(attn_gemm_kernel, cudaFuncAttributeMaxDynamicSharedMemorySize, DYN_SMEM);

    pack_kernel<<<256, 256>>>(dt, st, U);
    wq_kernel<<<64, 128>>>(W);
    attn_gemm_kernel<<<1024, 512, DYN_SMEM>>>(H, v, out);
    softmax_kernel<<<128, 256>>>(out);
}